// round 6
// baseline (speedup 1.0000x reference)
#include <cuda_runtime.h>

#define Bv 1024
#define Tv 512
#define Kv 48
#define BPB 7                  // batches per block
#define FWD_T (BPB * Kv)       // 336 forward threads
#define TPB 384                // 12 warps -> 3 per SMSP

__device__ __forceinline__ unsigned long long fma2(unsigned long long a,
                                                   unsigned long long b,
                                                   unsigned long long c) {
    unsigned long long d;
    asm("fma.rn.f32x2 %0, %1, %2, %3;" : "=l"(d) : "l"(a), "l"(b), "l"(c));
    return d;
}
__device__ __forceinline__ unsigned long long add2(unsigned long long a,
                                                   unsigned long long b) {
    unsigned long long d;
    asm("add.rn.f32x2 %0, %1, %2;" : "=l"(d) : "l"(a), "l"(b));
    return d;
}
__device__ __forceinline__ unsigned long long pack2(float lo, float hi) {
    unsigned long long d;
    asm("mov.b64 %0, {%1, %2};" : "=l"(d) : "f"(lo), "f"(hi));
    return d;
}
__device__ __forceinline__ void unpack2(unsigned long long v, float& lo, float& hi) {
    asm("mov.b64 {%0, %1}, %2;" : "=f"(lo), "=f"(hi) : "l"(v));
}

// CRF nll = log_norm - score, fused single kernel.
// Forward algorithm in scaled-linear space:
//   s_j <- (sum_i s_i * E_ij) * exp(e_tj),   E = exp(trans)   (exact algebra)
// renormalized by the batch-uniform scale S = s_0 every 4th step (c += log S).
// 48 fwd threads per batch; thread j holds E column j as 24 packed f32x2
// registers -> 24 FFMA2 per step. Threads >= FWD_T walk the label chains
// (sequence score), paced by the same per-step barrier; their emission
// gathers hit lines the forward threads prefetched two steps earlier.
__global__ void __launch_bounds__(TPB, 1) crf_kernel(
    const float* __restrict__ emis,    // [B,T,K]
    const int*   __restrict__ labels,  // [B,T]
    const float* __restrict__ trans,   // [K,K]
    float* __restrict__ out)           // [B]
{
    __shared__ __align__(16) float sA[2][BPB][Kv];   // double-buffered alpha rows
    __shared__ float sScore[BPB];

    const int tid    = threadIdx.x;
    const bool isfwd = tid < FWD_T;

    // ---------------- forward-thread state ----------------
    int bl = 0, j = 0, b = 0;
    bool fact = false;
    unsigned long long Ecol2[24];
    const float* ebj = emis;
    float s = 0.f, c = 0.f, e_cur = 0.f, e_nxt = 0.f;

    // ---------------- score-thread state ----------------
    const int si = tid - FWD_T;             // 0..47
    bool sact = false;
    const float* seb = emis;
    const int*   slb = labels;
    int l_prev = 0, l_cur = 0;
    float acc = 0.f;

    if (isfwd) {
        bl = tid / Kv;
        j  = tid - bl * Kv;
        b  = blockIdx.x * BPB + bl;
        fact = (b < Bv);
        const int bs = fact ? b : 0;
        #pragma unroll
        for (int i = 0; i < 24; i++)
            Ecol2[i] = pack2(__expf(trans[(2 * i) * Kv + j]),
                             __expf(trans[(2 * i + 1) * Kv + j]));
        ebj = emis + (size_t)bs * Tv * Kv + j;
        s = __expf(ebj[0]);                 // t = 0
        e_cur = ebj[Kv];                    // prefetch t=1, t=2
        e_nxt = ebj[2 * Kv];
    } else if (si < BPB) {
        const int sb = blockIdx.x * BPB + si;
        sact = (sb < Bv);
        const int bs = sact ? sb : 0;
        seb = emis + (size_t)bs * Tv * Kv;
        slb = labels + (size_t)bs * Tv;
        l_prev = slb[0];
        l_cur  = slb[1];
        acc = seb[l_prev];                  // unary t = 0
    }

    int buf = 0;

    // One step of the recurrence. RES/GUARD become compile-time constants.
    auto step = [&](int t, bool RES, bool GUARD) {
        float e_fut = 0.0f;
        if (isfwd) {
            // issue next prefetch BEFORE the barrier: in flight during the wait
            if (!GUARD || (t + 2 < Tv)) e_fut = ebj[(size_t)(t + 2) * Kv];
            sA[buf][bl][j] = s;
        } else if (sact) {
            int l_next = (t + 1 < Tv) ? slb[t + 1] : 0;
            acc += trans[l_prev * Kv + l_cur];           // binary (t-1) -> t
            acc += seb[(size_t)t * Kv + l_cur];          // unary t (cache-hot)
            l_prev = l_cur;
            l_cur  = l_next;
        }
        __syncthreads();                    // single unconditional barrier
        if (isfwd) {
            const float* row = sA[buf][bl];
            const ulonglong2* rv = (const ulonglong2*)row;   // LDS.128 broadcast
            unsigned long long a0 = 0ull, a1 = 0ull, a2 = 0ull, a3 = 0ull;
            #pragma unroll
            for (int i = 0; i < 6; i++) {
                ulonglong2 v = rv[i];
                a0 = fma2(v.x, Ecol2[2 * i],     a0);
                a1 = fma2(v.y, Ecol2[2 * i + 1], a1);
            }
            #pragma unroll
            for (int i = 6; i < 12; i++) {
                ulonglong2 v = rv[i];
                a2 = fma2(v.x, Ecol2[2 * i],     a2);
                a3 = fma2(v.y, Ecol2[2 * i + 1], a3);
            }
            a0 = add2(a0, a2);
            a1 = add2(a1, a3);
            a0 = add2(a0, a1);
            float lo, hi; unpack2(a0, lo, hi);
            float usum = (lo + hi) * __expf(e_cur);
            if (RES) {
                float S = row[0];           // batch-uniform positive scale
                c += __logf(S);
                s = usum * __fdividef(1.0f, S);
            } else {
                s = usum;
            }
            e_cur = e_nxt;
            e_nxt = e_fut;
        }
        buf ^= 1;
    };

    // t = 1 .. 508 unrolled by 4 (rescale when t % 4 == 0); tail t = 509..511
    for (int k = 0; k < 127; k++) {
        int t = 4 * k + 1;
        step(t,     false, false);
        step(t + 1, false, false);
        step(t + 2, false, false);
        step(t + 3, true,  false);
    }
    step(509, false, true);
    step(510, false, true);
    step(511, false, true);

    // ---- final: out = c + log(sum_j s_j) - score ----
    if (isfwd)           sA[buf][bl][j] = s;
    else if (si < BPB)   sScore[si] = acc;
    __syncthreads();

    if (isfwd && j == 0 && fact) {
        const float4* av = (const float4*)sA[buf][bl];
        float4 t0 = av[0];
        float ssum = (t0.x + t0.y) + (t0.z + t0.w);
        #pragma unroll
        for (int i = 1; i < Kv / 4; i++) {
            float4 a4 = av[i];
            ssum += (a4.x + a4.y) + (a4.z + a4.w);
        }
        out[b] = c + __logf(ssum) - sScore[bl];
    }
}

extern "C" void kernel_launch(void* const* d_in, const int* in_sizes, int n_in,
                              void* d_out, int out_size) {
    const float* emis   = (const float*)d_in[0];   // output: [B,T,K] fp32
    const int*   labels = (const int*)d_in[1];     // label_input: [B,T] int32
    const float* trans  = (const float*)d_in[2];   // transition_params: [K,K] fp32
    float* out = (float*)d_out;                    // [B] fp32

    crf_kernel<<<(Bv + BPB - 1) / BPB, TPB>>>(emis, labels, trans, out);
}